// round 1
// baseline (speedup 1.0000x reference)
#include <cuda_runtime.h>
#include <cuda_bf16.h>
#include <math.h>

// ---------------- problem constants ----------------
#define NIMG 16
#define CDIM 512
#define HDIM 32
#define WDIM 32
#define TTOK (NIMG*HDIM*WDIM)      // 16384
#define MEMN 2000
#define MEMP 2048                   // padded
#define CHID 256
#define SHRINK 0.0025f
#define EPSV 1e-12f

#define OUT_ELEMS ((size_t)NIMG*CDIM*HDIM*WDIM)   // 8388608

// ---------------- scratch (device globals; no allocation allowed) ----------------
__device__ float g_q[(size_t)TTOK * CDIM];        // 32 MB  normalized queries [T,C]
__device__ float g_h[(size_t)MEMN * CHID];        // 2 MB   MLP hidden
__device__ float g_m[(size_t)MEMN * CDIM];        // 4 MB   MLP out (pre-norm)
__device__ float g_mnorm[(size_t)MEMP * CDIM];    // 4 MB   normalized memory, zero padded rows
__device__ float g_Z[TTOK];                       // softmax denominators
__device__ float g_L1[TTOK];                      // post-shrink L1 sums

// ---------------- kernel 0: zero Z ----------------
__global__ void zero_z_kernel() {
    int i = blockIdx.x * blockDim.x + threadIdx.x;
    if (i < TTOK) g_Z[i] = 0.0f;
}

// ---------------- kernel 1: build q (NCHW -> [T,C], L2 normalized) ----------------
// one block per (n,h): 32 tokens (w = 0..31)
__global__ void build_q_kernel(const float* __restrict__ x) {
    int bid = blockIdx.x;            // n*32 + h
    int n = bid >> 5, h = bid & 31;
    int tid = threadIdx.x;           // 256 threads
    int w = tid & 31, cg = tid >> 5; // cg 0..7

    __shared__ float ss[8][32];
    __shared__ float inv[32];
    __shared__ float xt[32][33];

    const float* xb = x + (size_t)n * (CDIM * HDIM * WDIM) + h * WDIM; // xb[c*1024 + w]

    float part = 0.0f;
    for (int c = cg; c < CDIM; c += 8) {
        float v = xb[c * 1024 + w];
        part += v * v;
    }
    ss[cg][w] = part;
    __syncthreads();
    if (tid < 32) {
        float s = 0.0f;
        #pragma unroll
        for (int g = 0; g < 8; g++) s += ss[g][tid];
        inv[tid] = 1.0f / fmaxf(sqrtf(s), EPSV);
    }
    __syncthreads();

    int t0 = n * 1024 + h * 32;
    int cl = tid & 31, tg = tid >> 5;
    for (int c0 = 0; c0 < CDIM; c0 += 32) {
        for (int ci = cg; ci < 32; ci += 8)
            xt[ci][w] = xb[(c0 + ci) * 1024 + w];
        __syncthreads();
        for (int tl = tg; tl < 32; tl += 8)
            g_q[(size_t)(t0 + tl) * CDIM + c0 + cl] = xt[cl][tl] * inv[tl];
        __syncthreads();
    }
}

// ---------------- kernel 2: MLP GEMM  C[M,N] = relu(A[M,K] @ B[N,K]^T + bias) ----------------
// BM=BN=64, BK=32, 256 threads, 4x4 micro-tile
__global__ void mlp_gemm_kernel(const float* __restrict__ extA,
                                const float* __restrict__ Bw,
                                const float* __restrict__ bias,
                                int layer) {
    const float* A = layer ? (const float*)g_h : extA;
    float* Cc      = layer ? g_m : g_h;
    const int M = MEMN;
    const int N = layer ? CDIM : CHID;
    const int K = layer ? CHID : CDIM;

    int n0 = blockIdx.x * 64;
    int m0 = blockIdx.y * 64;

    __shared__ float As[64][33];
    __shared__ float Bs[64][33];

    int tid = threadIdx.x;
    int tx = tid & 15, ty = tid >> 4;
    float acc[4][4] = {};

    for (int k0 = 0; k0 < K; k0 += 32) {
        for (int idx = tid; idx < 512; idx += 256) {
            int r = idx >> 3, kq = (idx & 7) << 2;
            float4 v = make_float4(0.f, 0.f, 0.f, 0.f);
            if (m0 + r < M) v = *(const float4*)&A[(size_t)(m0 + r) * K + k0 + kq];
            As[r][kq + 0] = v.x; As[r][kq + 1] = v.y; As[r][kq + 2] = v.z; As[r][kq + 3] = v.w;
        }
        for (int idx = tid; idx < 512; idx += 256) {
            int r = idx >> 3, kq = (idx & 7) << 2;
            float4 v = *(const float4*)&Bw[(size_t)(n0 + r) * K + k0 + kq];
            Bs[r][kq + 0] = v.x; Bs[r][kq + 1] = v.y; Bs[r][kq + 2] = v.z; Bs[r][kq + 3] = v.w;
        }
        __syncthreads();
        for (int kk = 0; kk < 32; kk++) {
            float a[4], b[4];
            #pragma unroll
            for (int i = 0; i < 4; i++) a[i] = As[tx * 4 + i][kk];
            #pragma unroll
            for (int j = 0; j < 4; j++) b[j] = Bs[ty * 4 + j][kk];
            #pragma unroll
            for (int i = 0; i < 4; i++)
                #pragma unroll
                for (int j = 0; j < 4; j++)
                    acc[i][j] += a[i] * b[j];
        }
        __syncthreads();
    }

    #pragma unroll
    for (int j = 0; j < 4; j++) {
        int col = n0 + ty * 4 + j;
        float bv = bias[col];
        #pragma unroll
        for (int i = 0; i < 4; i++) {
            int row = m0 + tx * 4 + i;
            if (row < M) Cc[(size_t)row * N + col] = fmaxf(acc[i][j] + bv, 0.0f);
        }
    }
}

// ---------------- kernel 3: row L2-normalize m -> g_mnorm (zero pad rows >= 2000) ----------------
__global__ void norm_rows_kernel() {
    int row = blockIdx.x;    // 0..2047
    int tid = threadIdx.x;   // 256
    float* dst = &g_mnorm[(size_t)row * CDIM];
    if (row >= MEMN) {
        dst[tid] = 0.0f; dst[tid + 256] = 0.0f;
        return;
    }
    const float* src = &g_m[(size_t)row * CDIM];
    float v0 = src[tid], v1 = src[tid + 256];
    float ssv = v0 * v0 + v1 * v1;
    #pragma unroll
    for (int o = 16; o > 0; o >>= 1) ssv += __shfl_down_sync(0xffffffffu, ssv, o);
    __shared__ float red[8];
    __shared__ float sinv;
    if ((tid & 31) == 0) red[tid >> 5] = ssv;
    __syncthreads();
    if (tid == 0) {
        float s = 0.0f;
        #pragma unroll
        for (int i = 0; i < 8; i++) s += red[i];
        sinv = 1.0f / fmaxf(sqrtf(s), EPSV);
    }
    __syncthreads();
    dst[tid] = v0 * sinv;
    dst[tid + 256] = v1 * sinv;
}

// ---------------- kernel 4: scores  e = exp(q @ m_norm^T), Z = row sums ----------------
// BM=128 tokens, BN=128 mems, BK=32, 256 threads, 8x8 micro-tile
__global__ __launch_bounds__(256) void attn_scores_kernel(float* __restrict__ att) {
    int j0 = blockIdx.x * 128;      // mem tile (0..15), covers padded 2048
    int t0 = blockIdx.y * 128;      // token tile

    __shared__ float As[128][34];
    __shared__ float Bs[128][34];
    __shared__ float zred[16][128];

    int tid = threadIdx.x;
    int tx = tid & 15, ty = tid >> 4;
    float acc[8][8] = {};

    for (int k0 = 0; k0 < CDIM; k0 += 32) {
        for (int idx = tid; idx < 1024; idx += 256) {
            int r = idx >> 3, kq = (idx & 7) << 2;
            float4 v = *(const float4*)&g_q[(size_t)(t0 + r) * CDIM + k0 + kq];
            As[r][kq + 0] = v.x; As[r][kq + 1] = v.y; As[r][kq + 2] = v.z; As[r][kq + 3] = v.w;
        }
        for (int idx = tid; idx < 1024; idx += 256) {
            int r = idx >> 3, kq = (idx & 7) << 2;
            float4 v = *(const float4*)&g_mnorm[(size_t)(j0 + r) * CDIM + k0 + kq];
            Bs[r][kq + 0] = v.x; Bs[r][kq + 1] = v.y; Bs[r][kq + 2] = v.z; Bs[r][kq + 3] = v.w;
        }
        __syncthreads();
        for (int kk = 0; kk < 32; kk++) {
            float a[8], b[8];
            #pragma unroll
            for (int i = 0; i < 8; i++) a[i] = As[tx * 8 + i][kk];
            #pragma unroll
            for (int j = 0; j < 8; j++) b[j] = Bs[ty * 8 + j][kk];
            #pragma unroll
            for (int i = 0; i < 8; i++)
                #pragma unroll
                for (int j = 0; j < 8; j++)
                    acc[i][j] += a[i] * b[j];
        }
        __syncthreads();
    }

    // epilogue: e = exp(score); write to att scratch (final att_r layout); accumulate Z
    int n = t0 >> 10, hw0 = t0 & 1023;
    float zpart[8] = {};
    #pragma unroll
    for (int jj = 0; jj < 8; jj++) {
        int j = j0 + ty * 8 + jj;
        if (j < MEMN) {
            float* dst = att + (((size_t)(n * MEMN + j)) << 10) + hw0 + tx * 8;
            #pragma unroll
            for (int i = 0; i < 8; i++) {
                float e = expf(acc[i][jj]);
                dst[i] = e;
                zpart[i] += e;
            }
        }
    }
    #pragma unroll
    for (int i = 0; i < 8; i++) zred[ty][tx * 8 + i] = zpart[i];
    __syncthreads();
    if (tid < 128) {
        float s = 0.0f;
        #pragma unroll
        for (int g = 0; g < 16; g++) s += zred[g][tid];
        atomicAdd(&g_Z[t0 + tid], s);
    }
}

// ---------------- kernel 5: out = (p @ m_norm) / L1,  p = relu(e/Z - SHRINK) ----------------
// BM=128 tokens, BN=128 channels, BK=32 mems over padded K=2048
__global__ __launch_bounds__(256) void attn_out_kernel(const float* __restrict__ att,
                                                       float* __restrict__ out) {
    int c0 = blockIdx.x * 128;     // channel tile (0..3)
    int t0 = blockIdx.y * 128;     // token tile
    int n = t0 >> 10, hw0 = t0 & 1023;

    __shared__ float Ap[128][34];
    __shared__ float Bsm[32][128];
    __shared__ float zinv[128];
    __shared__ float l1red[2][128];
    __shared__ float l1inv[128];

    int tid = threadIdx.x;
    int tx = tid & 15, ty = tid >> 4;

    if (tid < 128) zinv[tid] = 1.0f / g_Z[t0 + tid];
    __syncthreads();

    int tok = tid & 127, jg = tid >> 7;     // loader roles
    float ziv = zinv[tok];
    float l1part = 0.0f;
    float acc[8][8] = {};
    const float* ebase = att + (((size_t)n * MEMN) << 10) + hw0;

    for (int jk0 = 0; jk0 < MEMP; jk0 += 32) {
        #pragma unroll
        for (int jj = 0; jj < 16; jj++) {
            int jl = jg * 16 + jj;
            int j = jk0 + jl;
            float e = (j < MEMN) ? ebase[((size_t)j << 10) + tok] : 0.0f;
            float p = fmaxf(e * ziv - SHRINK, 0.0f);
            Ap[tok][jl] = p;
            l1part += p;
        }
        #pragma unroll
        for (int jj = 0; jj < 16; jj++) {
            int jl = jg * 16 + jj;
            Bsm[jl][tok] = g_mnorm[(size_t)(jk0 + jl) * CDIM + c0 + tok];
        }
        __syncthreads();
        for (int kk = 0; kk < 32; kk++) {
            float a[8], b[8];
            #pragma unroll
            for (int i = 0; i < 8; i++) a[i] = Ap[tx * 8 + i][kk];
            #pragma unroll
            for (int j = 0; j < 8; j++) b[j] = Bsm[kk][ty * 8 + j];
            #pragma unroll
            for (int i = 0; i < 8; i++)
                #pragma unroll
                for (int j = 0; j < 8; j++)
                    acc[i][j] += a[i] * b[j];
        }
        __syncthreads();
    }

    l1red[jg][tok] = l1part;
    __syncthreads();
    if (tid < 128) {
        float L1 = l1red[0][tid] + l1red[1][tid];
        l1inv[tid] = 1.0f / fmaxf(L1, EPSV);
        if (c0 == 0) g_L1[t0 + tid] = L1;
    }
    __syncthreads();

    // write out in NCHW: out[((n*C + c)*H + h)*W + w], tokens contiguous in hw
    #pragma unroll
    for (int jj = 0; jj < 8; jj++) {
        int c = c0 + ty * 8 + jj;
        float* dst = out + (((size_t)(n * CDIM + c)) << 10) + hw0 + tx * 8;
        #pragma unroll
        for (int i = 0; i < 8; i++)
            dst[i] = acc[i][jj] * l1inv[tx * 8 + i];
    }
}

// ---------------- kernel 6: finalize att_r = relu(e/Z - SHRINK)/max(L1,eps) in place ----------------
__global__ void att_finalize_kernel(float* __restrict__ att) {
    int b = blockIdx.x;           // n*MEMN + j  (0..31999)
    int n = b / MEMN;
    int tid = threadIdx.x;        // 256 threads, 4 floats each
    size_t base = ((size_t)b << 10) + (tid << 2);
    int t = (n << 10) + (tid << 2);

    float4 e = *(float4*)&att[base];
    float4 z = *(const float4*)&g_Z[t];
    float4 l = *(const float4*)&g_L1[t];

    float4 r;
    r.x = fmaxf(e.x * (1.0f / z.x) - SHRINK, 0.0f) * (1.0f / fmaxf(l.x, EPSV));
    r.y = fmaxf(e.y * (1.0f / z.y) - SHRINK, 0.0f) * (1.0f / fmaxf(l.y, EPSV));
    r.z = fmaxf(e.z * (1.0f / z.z) - SHRINK, 0.0f) * (1.0f / fmaxf(l.z, EPSV));
    r.w = fmaxf(e.w * (1.0f / z.w) - SHRINK, 0.0f) * (1.0f / fmaxf(l.w, EPSV));
    *(float4*)&att[base] = r;
}

// ---------------- launch ----------------
extern "C" void kernel_launch(void* const* d_in, const int* in_sizes, int n_in,
                              void* d_out, int out_size) {
    const float* x      = (const float*)d_in[0];   // [16,512,32,32]
    const float* memory = (const float*)d_in[1];   // [2000,512]
    const float* w1     = (const float*)d_in[2];   // [256,512]
    const float* b1     = (const float*)d_in[3];   // [256]
    const float* w2     = (const float*)d_in[4];   // [512,256]
    const float* b2     = (const float*)d_in[5];   // [512]

    float* out = (float*)d_out;                    // output [16,512,32,32]
    float* att = out + OUT_ELEMS;                  // att_r  [16,2000,32,32]

    zero_z_kernel<<<TTOK / 256, 256>>>();
    build_q_kernel<<<NIMG * HDIM, 256>>>(x);
    mlp_gemm_kernel<<<dim3(CHID / 64, (MEMN + 63) / 64), 256>>>(memory, w1, b1, 0);
    mlp_gemm_kernel<<<dim3(CDIM / 64, (MEMN + 63) / 64), 256>>>(nullptr, w2, b2, 1);
    norm_rows_kernel<<<MEMP, 256>>>();
    attn_scores_kernel<<<dim3(MEMP / 128, TTOK / 128), 256>>>(att);
    attn_out_kernel<<<dim3(CDIM / 128, TTOK / 128), 256>>>(att, out);
    att_finalize_kernel<<<NIMG * MEMN, 256>>>(att);
}

// round 3
// speedup vs baseline: 6.4727x; 6.4727x over previous
#include <cuda_runtime.h>
#include <cuda_bf16.h>
#include <cstdint>
#include <math.h>

// ---------------- problem constants ----------------
#define NIMG 16
#define CDIM 512
#define HDIM 32
#define WDIM 32
#define TTOK (NIMG*HDIM*WDIM)      // 16384
#define MEMN 2000
#define MEMP 2048                   // padded
#define CHID 256
#define SHRINK 0.0025f
#define EPSV 1e-12f

#define OUT_ELEMS ((size_t)NIMG*CDIM*HDIM*WDIM)   // 8388608

// ---------------- scratch (device globals) ----------------
__device__ float g_q[(size_t)TTOK * CDIM];        // tf32-rounded queries [T,C]
__device__ float g_h[(size_t)MEMN * CHID];        // MLP hidden
__device__ float g_m[(size_t)MEMN * CDIM];        // MLP out (pre-norm)
__device__ float g_mnorm[(size_t)MEMP * CDIM];    // normalized memory [J,C], tf32, zero pad
__device__ float g_mnormT[(size_t)CDIM * MEMP];   // transposed [C,J], tf32, zero pad
__device__ float g_Z[TTOK];
__device__ float g_L1[TTOK];

__device__ __forceinline__ float to_tf32(float x) {
    uint32_t u;
    asm("cvt.rna.tf32.f32 %0, %1;" : "=r"(u) : "f"(x));
    return __uint_as_float(u);
}

#define MMA_TF32(c, a, b) \
    asm volatile("mma.sync.aligned.m16n8k8.row.col.f32.tf32.tf32.f32 " \
        "{%0,%1,%2,%3}, {%4,%5,%6,%7}, {%8,%9}, {%0,%1,%2,%3};" \
        : "+f"((c)[0]), "+f"((c)[1]), "+f"((c)[2]), "+f"((c)[3]) \
        : "r"((a)[0]), "r"((a)[1]), "r"((a)[2]), "r"((a)[3]), \
          "r"((b)[0]), "r"((b)[1]))

// ---------------- kernel: zero Z ----------------
__global__ void zero_z_kernel() {
    int i = blockIdx.x * blockDim.x + threadIdx.x;
    if (i < TTOK) g_Z[i] = 0.0f;
}

// ---------------- kernel: build q (NCHW -> [T,C], L2 normalized, tf32) ----------------
__global__ void build_q_kernel(const float* __restrict__ x) {
    int bid = blockIdx.x;
    int n = bid >> 5, h = bid & 31;
    int tid = threadIdx.x;
    int w = tid & 31, cg = tid >> 5;

    __shared__ float ss[8][32];
    __shared__ float inv[32];
    __shared__ float xt[32][33];

    const float* xb = x + (size_t)n * (CDIM * HDIM * WDIM) + h * WDIM;

    float part = 0.0f;
    for (int c = cg; c < CDIM; c += 8) {
        float v = xb[c * 1024 + w];
        part += v * v;
    }
    ss[cg][w] = part;
    __syncthreads();
    if (tid < 32) {
        float s = 0.0f;
        #pragma unroll
        for (int g = 0; g < 8; g++) s += ss[g][tid];
        inv[tid] = 1.0f / fmaxf(sqrtf(s), EPSV);
    }
    __syncthreads();

    int t0 = n * 1024 + h * 32;
    int cl = tid & 31, tg = tid >> 5;
    for (int c0 = 0; c0 < CDIM; c0 += 32) {
        for (int ci = cg; ci < 32; ci += 8)
            xt[ci][w] = xb[(c0 + ci) * 1024 + w];
        __syncthreads();
        for (int tl = tg; tl < 32; tl += 8)
            g_q[(size_t)(t0 + tl) * CDIM + c0 + cl] = to_tf32(xt[cl][tl] * inv[tl]);
        __syncthreads();
    }
}

// ---------------- kernel: MLP GEMM  C = relu(A @ B^T + bias) ----------------
__global__ void mlp_gemm_kernel(const float* __restrict__ extA,
                                const float* __restrict__ Bw,
                                const float* __restrict__ bias,
                                int layer) {
    const float* A = layer ? (const float*)g_h : extA;
    float* Cc      = layer ? g_m : g_h;
    const int M = MEMN;
    const int N = layer ? CDIM : CHID;
    const int K = layer ? CHID : CDIM;

    int n0 = blockIdx.x * 64;
    int m0 = blockIdx.y * 64;

    __shared__ float As[64][33];
    __shared__ float Bs[64][33];

    int tid = threadIdx.x;
    int tx = tid & 15, ty = tid >> 4;
    float acc[4][4] = {};

    for (int k0 = 0; k0 < K; k0 += 32) {
        for (int idx = tid; idx < 512; idx += 256) {
            int r = idx >> 3, kq = (idx & 7) << 2;
            float4 v = make_float4(0.f, 0.f, 0.f, 0.f);
            if (m0 + r < M) v = *(const float4*)&A[(size_t)(m0 + r) * K + k0 + kq];
            As[r][kq + 0] = v.x; As[r][kq + 1] = v.y; As[r][kq + 2] = v.z; As[r][kq + 3] = v.w;
        }
        for (int idx = tid; idx < 512; idx += 256) {
            int r = idx >> 3, kq = (idx & 7) << 2;
            float4 v = *(const float4*)&Bw[(size_t)(n0 + r) * K + k0 + kq];
            Bs[r][kq + 0] = v.x; Bs[r][kq + 1] = v.y; Bs[r][kq + 2] = v.z; Bs[r][kq + 3] = v.w;
        }
        __syncthreads();
        for (int kk = 0; kk < 32; kk++) {
            float a[4], b[4];
            #pragma unroll
            for (int i = 0; i < 4; i++) a[i] = As[tx * 4 + i][kk];
            #pragma unroll
            for (int j = 0; j < 4; j++) b[j] = Bs[ty * 4 + j][kk];
            #pragma unroll
            for (int i = 0; i < 4; i++)
                #pragma unroll
                for (int j = 0; j < 4; j++)
                    acc[i][j] += a[i] * b[j];
        }
        __syncthreads();
    }

    #pragma unroll
    for (int j = 0; j < 4; j++) {
        int col = n0 + ty * 4 + j;
        float bv = bias[col];
        #pragma unroll
        for (int i = 0; i < 4; i++) {
            int row = m0 + tx * 4 + i;
            if (row < M) Cc[(size_t)row * N + col] = fmaxf(acc[i][j] + bv, 0.0f);
        }
    }
}

// ---------------- kernel: row L2-normalize m -> g_mnorm (tf32, zero pad) ----------------
__global__ void norm_rows_kernel() {
    int row = blockIdx.x;
    int tid = threadIdx.x;
    float* dst = &g_mnorm[(size_t)row * CDIM];
    if (row >= MEMN) {
        dst[tid] = 0.0f; dst[tid + 256] = 0.0f;
        return;
    }
    const float* src = &g_m[(size_t)row * CDIM];
    float v0 = src[tid], v1 = src[tid + 256];
    float ssv = v0 * v0 + v1 * v1;
    #pragma unroll
    for (int o = 16; o > 0; o >>= 1) ssv += __shfl_down_sync(0xffffffffu, ssv, o);
    __shared__ float red[8];
    __shared__ float sinv;
    if ((tid & 31) == 0) red[tid >> 5] = ssv;
    __syncthreads();
    if (tid == 0) {
        float s = 0.0f;
        #pragma unroll
        for (int i = 0; i < 8; i++) s += red[i];
        sinv = 1.0f / fmaxf(sqrtf(s), EPSV);
    }
    __syncthreads();
    dst[tid] = to_tf32(v0 * sinv);
    dst[tid + 256] = to_tf32(v1 * sinv);
}

// ---------------- kernel: transpose g_mnorm [J,C] -> g_mnormT [C,J] ----------------
__global__ void transpose_m_kernel() {
    __shared__ float t[32][33];
    int j0 = blockIdx.x * 32, c0 = blockIdx.y * 32;
    int lx = threadIdx.x, ly = threadIdx.y;   // 32 x 8
    #pragma unroll
    for (int ry = 0; ry < 32; ry += 8)
        t[ly + ry][lx] = g_mnorm[(size_t)(j0 + ly + ry) * CDIM + c0 + lx];
    __syncthreads();
    #pragma unroll
    for (int ry = 0; ry < 32; ry += 8)
        g_mnormT[(size_t)(c0 + ly + ry) * MEMP + j0 + lx] = t[lx][ly + ry];
}

// ================ mma.sync tf32 scores kernel ==================
// tile: 128 tokens x 128 mems, K=512, BK=32; 8 warps (2m x 4n), warp tile 64x32
// epilogue: e = exp(score) -> att (att_r layout), Z reduction
__global__ __launch_bounds__(256, 2) void attn_scores_mma(float* __restrict__ att) {
    const int j0 = blockIdx.x * 128;
    const int t0 = blockIdx.y * 128;

    __shared__ float As[128][36];
    __shared__ float Bs[128][36];
    __shared__ float zsum[128];

    const int tid = threadIdx.x;
    const int lane = tid & 31, wid = tid >> 5;
    const int wm = wid & 1, wn = wid >> 1;
    const int g = lane >> 2, tg = lane & 3;

    if (tid < 128) zsum[tid] = 0.0f;

    float acc[4][4][4] = {};

    for (int k0 = 0; k0 < CDIM; k0 += 32) {
        #pragma unroll
        for (int i = 0; i < 4; i++) {
            int idx = tid + i * 256;
            int r = idx >> 3, q = (idx & 7) * 4;
            *(float4*)&As[r][q] = *(const float4*)&g_q[(size_t)(t0 + r) * CDIM + k0 + q];
            *(float4*)&Bs[r][q] = *(const float4*)&g_mnorm[(size_t)(j0 + r) * CDIM + k0 + q];
        }
        __syncthreads();
        #pragma unroll
        for (int kk = 0; kk < 32; kk += 8) {
            uint32_t a[4][4], b[4][2];
            #pragma unroll
            for (int i = 0; i < 4; i++) {
                const float* ap = &As[wm * 64 + i * 16 + g][kk + tg];
                a[i][0] = __float_as_uint(ap[0]);
                a[i][1] = __float_as_uint(ap[8 * 36]);
                a[i][2] = __float_as_uint(ap[4]);
                a[i][3] = __float_as_uint(ap[8 * 36 + 4]);
            }
            #pragma unroll
            for (int j = 0; j < 4; j++) {
                const float* bp = &Bs[wn * 32 + j * 8 + g][kk + tg];
                b[j][0] = __float_as_uint(bp[0]);
                b[j][1] = __float_as_uint(bp[4]);
            }
            #pragma unroll
            for (int i = 0; i < 4; i++)
                #pragma unroll
                for (int j = 0; j < 4; j++)
                    MMA_TF32(acc[i][j], a[i], b[j]);
        }
        __syncthreads();
    }

    // epilogue
    const int n = t0 >> 10, hwb = t0 & 1023;
    #pragma unroll
    for (int i = 0; i < 4; i++) {
        int r0 = wm * 64 + i * 16 + g;
        float z0 = 0.0f, z1 = 0.0f;
        #pragma unroll
        for (int j = 0; j < 4; j++) {
            int cb = wn * 32 + j * 8 + 2 * tg;
            #pragma unroll
            for (int cc = 0; cc < 2; cc++) {
                int jj = j0 + cb + cc;
                if (jj < MEMN) {
                    float e0 = __expf(acc[i][j][cc]);
                    float e1 = __expf(acc[i][j][cc + 2]);
                    size_t base = ((size_t)(n * MEMN + jj)) << 10;
                    att[base + hwb + r0] = e0;
                    att[base + hwb + r0 + 8] = e1;
                    z0 += e0; z1 += e1;
                }
            }
        }
        z0 += __shfl_xor_sync(0xffffffffu, z0, 1);
        z0 += __shfl_xor_sync(0xffffffffu, z0, 2);
        z1 += __shfl_xor_sync(0xffffffffu, z1, 1);
        z1 += __shfl_xor_sync(0xffffffffu, z1, 2);
        if (tg == 0) {
            atomicAdd(&zsum[r0], z0);
            atomicAdd(&zsum[r0 + 8], z1);
        }
    }
    __syncthreads();
    if (tid < 128) atomicAdd(&g_Z[t0 + tid], zsum[tid]);
}

// ================ mma.sync tf32 out kernel ==================
// tile: 128 tokens x 128 channels, K=2048 mems, BK=32
// A = p = relu(e/Z - SHRINK) built on the fly (accumulates L1); B = g_mnormT
__global__ __launch_bounds__(256, 2) void attn_out_mma(const float* __restrict__ att,
                                                       float* __restrict__ out) {
    const int c0b = blockIdx.x * 128;
    const int t0 = blockIdx.y * 128;
    const int n = t0 >> 10, hw0 = t0 & 1023;

    __shared__ float Ap[128][36];
    __shared__ float Bs[128][36];
    __shared__ float zinv_s[128];
    __shared__ float l1p[256];
    __shared__ float l1inv[128];

    const int tid = threadIdx.x;
    const int lane = tid & 31, wid = tid >> 5;
    const int wm = wid & 1, wn = wid >> 1;
    const int g = lane >> 2, tg = lane & 3;

    if (tid < 128) zinv_s[tid] = 1.0f / g_Z[t0 + tid];
    __syncthreads();

    const int tok = tid & 127, jh = tid >> 7;
    const float ziv = zinv_s[tok];
    float l1 = 0.0f;
    const float* ebase = att + (((size_t)n * MEMN) << 10) + hw0 + tok;

    float acc[4][4][4] = {};

    for (int k0 = 0; k0 < MEMP; k0 += 32) {
        #pragma unroll
        for (int i = 0; i < 16; i++) {
            int jl = jh * 16 + i;
            int j = k0 + jl;
            float e = (j < MEMN) ? ebase[(size_t)j << 10] : 0.0f;
            float p = fmaxf(e * ziv - SHRINK, 0.0f);
            l1 += p;
            Ap[tok][jl] = to_tf32(p);
        }
        #pragma unroll
        for (int i = 0; i < 4; i++) {
            int idx = tid + i * 256;
            int r = idx >> 3, q = (idx & 7) * 4;
            *(float4*)&Bs[r][q] = *(const float4*)&g_mnormT[(size_t)(c0b + r) * MEMP + k0 + q];
        }
        __syncthreads();
        #pragma unroll
        for (int kk = 0; kk < 32; kk += 8) {
            uint32_t a[4][4], b[4][2];
            #pragma unroll
            for (int i = 0; i < 4; i++) {
                const float* ap = &Ap[wm * 64 + i * 16 + g][kk + tg];
                a[i][0] = __float_as_uint(ap[0]);
                a[i][1] = __float_as_uint(ap[8 * 36]);
                a[i][2] = __float_as_uint(ap[4]);
                a[i][3] = __float_as_uint(ap[8 * 36 + 4]);
            }
            #pragma unroll
            for (int j = 0; j < 4; j++) {
                const float* bp = &Bs[wn * 32 + j * 8 + g][kk + tg];
                b[j][0] = __float_as_uint(bp[0]);
                b[j][1] = __float_as_uint(bp[4]);
            }
            #pragma unroll
            for (int i = 0; i < 4; i++)
                #pragma unroll
                for (int j = 0; j < 4; j++)
                    MMA_TF32(acc[i][j], a[i], b[j]);
        }
        __syncthreads();
    }

    l1p[tid] = l1;
    __syncthreads();
    if (tid < 128) {
        float L1 = l1p[tid] + l1p[tid + 128];
        l1inv[tid] = 1.0f / fmaxf(L1, EPSV);
        if (c0b == 0) g_L1[t0 + tid] = L1;
    }
    __syncthreads();

    // epilogue: write out NCHW scaled by 1/L1
    #pragma unroll
    for (int i = 0; i < 4; i++) {
        int r0 = wm * 64 + i * 16 + g;
        float li0 = l1inv[r0], li1 = l1inv[r0 + 8];
        #pragma unroll
        for (int j = 0; j < 4; j++) {
            int cb = c0b + wn * 32 + j * 8 + 2 * tg;
            #pragma unroll
            for (int cc = 0; cc < 2; cc++) {
                size_t base = ((size_t)(n * CDIM + cb + cc)) << 10;
                out[base + hw0 + r0]     = acc[i][j][cc]     * li0;
                out[base + hw0 + r0 + 8] = acc[i][j][cc + 2] * li1;
            }
        }
    }
}

// ---------------- finalize att_r = relu(e/Z - SHRINK)/max(L1,eps) ----------------
__global__ void att_finalize_kernel(float* __restrict__ att) {
    int b = blockIdx.x;
    int n = b / MEMN;
    int tid = threadIdx.x;
    size_t base = ((size_t)b << 10) + (tid << 2);
    int t = (n << 10) + (tid << 2);

    float4 e = *(float4*)&att[base];
    float4 z = *(const float4*)&g_Z[t];
    float4 l = *(const float4*)&g_L1[t];

    float4 r;
    r.x = fmaxf(e.x * (1.0f / z.x) - SHRINK, 0.0f) * (1.0f / fmaxf(l.x, EPSV));
    r.y = fmaxf(e.y * (1.0f / z.y) - SHRINK, 0.0f) * (1.0f / fmaxf(l.y, EPSV));
    r.z = fmaxf(e.z * (1.0f / z.z) - SHRINK, 0.0f) * (1.0f / fmaxf(l.z, EPSV));
    r.w = fmaxf(e.w * (1.0f / z.w) - SHRINK, 0.0f) * (1.0f / fmaxf(l.w, EPSV));
    *(float4*)&att[base] = r;
}

// ---------------- launch ----------------
extern "C" void kernel_launch(void* const* d_in, const int* in_sizes, int n_in,
                              void* d_out, int out_size) {
    const float* x      = (const float*)d_in[0];
    const float* memory = (const float*)d_in[1];
    const float* w1     = (const float*)d_in[2];
    const float* b1     = (const float*)d_in[3];
    const float* w2     = (const float*)d_in[4];
    const float* b2     = (const float*)d_in[5];

    float* out = (float*)d_out;
    float* att = out + OUT_ELEMS;

    zero_z_kernel<<<TTOK / 256, 256>>>();
    build_q_kernel<<<NIMG * HDIM, 256>>>(x);
    mlp_gemm_kernel<<<dim3(CHID / 64, (MEMN + 63) / 64), 256>>>(memory, w1, b1, 0);
    mlp_gemm_kernel<<<dim3(CDIM / 64, (MEMN + 63) / 64), 256>>>(nullptr, w2, b2, 1);
    norm_rows_kernel<<<MEMP, 256>>>();
    transpose_m_kernel<<<dim3(MEMP / 32, CDIM / 32), dim3(32, 8)>>>();
    attn_scores_mma<<<dim3(MEMP / 128, TTOK / 128), 256>>>(att);
    attn_out_mma<<<dim3(CDIM / 128, TTOK / 128), 256>>>(att, out);
    att_finalize_kernel<<<NIMG * MEMN, 256>>>(att);
}